// round 1
// baseline (speedup 1.0000x reference)
#include <cuda_runtime.h>
#include <cuda_bf16.h>

#define N_NODES 17186
#define KTOP    12031
#define BATCH   64
#define NEDGE   500000
#define NTOT    (BATCH * N_NODES)
#define FIN     6
#define H1DIM   64
#define H2DIM   32

// ---------------- device scratch (static, no allocations) ----------------
__device__ int   g_is64;
__device__ int   g_degcnt[N_NODES];
__device__ int   g_off[N_NODES + 1];
__device__ int   g_cursor[N_NODES];
__device__ int   g_csr[NEDGE];
__device__ float g_dinv0[N_NODES];
__device__ float g_xw0[N_NODES * H1DIM];   // x@W1 (no bias), graph 0
__device__ float g_h1[N_NODES * H1DIM];    // relu(gcn1) for graph 0
__device__ float g_s0w[N_NODES];           // h1 @ Wp, graph 0
__device__ float g_score[NTOT];
__device__ unsigned char g_kept[NTOT];
__device__ float g_dinv2[N_NODES];
__device__ float g_xpw[N_NODES * H2DIM];   // tanh(score)*(h1@W2) for graph 0
__device__ float g_gmax[BATCH * H2DIM];

// ---------------- helpers ----------------
__device__ __forceinline__ int eidx(const void* ei, long long pos) {
    if (g_is64) return (int)((const long long*)ei)[pos];
    return ((const int*)ei)[pos];
}

__device__ __forceinline__ unsigned okey(float f) {
    unsigned u = __float_as_uint(f);
    u ^= (u & 0x80000000u) ? 0xFFFFFFFFu : 0x80000000u;
    return u;
}

// ---------------- kernels ----------------
__global__ void k_zero() {
    int i = blockIdx.x * blockDim.x + threadIdx.x;
    if (i < N_NODES) { g_degcnt[i] = 0; g_cursor[i] = 0; }
    if (i < BATCH * H2DIM) g_gmax[i] = 0.f;
}

__global__ void k_detect(const void* ei) {
    const long long* p = (const long long*)ei;
    int ok = 1;
    for (int i = 0; i < 8; i++) {
        long long v = p[i];
        if (v < 0 || v >= N_NODES) ok = 0;
    }
    g_is64 = ok;
}

__global__ void k_count(const void* ei) {
    int e = blockIdx.x * blockDim.x + threadIdx.x;
    if (e < NEDGE) {
        int d = eidx(ei, (long long)NEDGE + e);
        atomicAdd(&g_degcnt[d], 1);
    }
}

// single-block exclusive scan over g_degcnt -> g_off; also dinv0 = rsqrt(1+deg)
__global__ void k_scan() {
    __shared__ int sh[1024];
    __shared__ int sh_carry;
    int tid = threadIdx.x;
    if (tid == 0) sh_carry = 0;
    __syncthreads();
    for (int base = 0; base < N_NODES; base += 1024) {
        int idx = base + tid;
        int v = (idx < N_NODES) ? g_degcnt[idx] : 0;
        if (idx < N_NODES) g_dinv0[idx] = rsqrtf(1.0f + (float)v);
        sh[tid] = v;
        __syncthreads();
        for (int off = 1; off < 1024; off <<= 1) {
            int t = (tid >= off) ? sh[tid - off] : 0;
            __syncthreads();
            sh[tid] += t;
            __syncthreads();
        }
        int carry = sh_carry;
        if (idx < N_NODES) g_off[idx] = carry + sh[tid] - v;
        int total = sh[1023];
        __syncthreads();
        if (tid == 0) sh_carry = carry + total;
        __syncthreads();
    }
    if (tid == 0) g_off[N_NODES] = sh_carry;
}

__global__ void k_scatter(const void* ei) {
    int e = blockIdx.x * blockDim.x + threadIdx.x;
    if (e < NEDGE) {
        int d = eidx(ei, (long long)NEDGE + e);
        int s = eidx(ei, e);
        int pos = g_off[d] + atomicAdd(&g_cursor[d], 1);
        g_csr[pos] = s;
    }
}

// xw0 = x(graph0) @ W1  (raw, no bias)
__global__ void k_xw0(const float* __restrict__ data, const float* __restrict__ W1) {
    __shared__ float W1s[FIN * H1DIM];
    __shared__ float xs[4][8];
    int t = threadIdx.y * 64 + threadIdx.x;
    for (int i = t; i < FIN * H1DIM; i += 256) W1s[i] = W1[i];
    int node = blockIdx.x * 4 + threadIdx.y;
    if (threadIdx.x < FIN && node < N_NODES)
        xs[threadIdx.y][threadIdx.x] = data[node * FIN + threadIdx.x];
    __syncthreads();
    if (node < N_NODES) {
        int c = threadIdx.x;
        float acc = 0.f;
        #pragma unroll
        for (int k = 0; k < FIN; k++) acc += xs[threadIdx.y][k] * W1s[k * H1DIM + c];
        g_xw0[node * H1DIM + c] = acc;
    }
}

// h1 = relu(msg + self + b1); also s0w = h1 @ Wp  (one warp per node)
__global__ void k_h1(const float* __restrict__ b1, const float* __restrict__ Wp) {
    int w = (blockIdx.x * blockDim.x + threadIdx.x) >> 5;
    int lane = threadIdx.x & 31;
    if (w >= N_NODES) return;
    float dvi = g_dinv0[w];
    float selfw = dvi * dvi;
    float a0 = g_xw0[w * 64 + lane] * selfw;
    float a1 = g_xw0[w * 64 + 32 + lane] * selfw;
    int s = g_off[w], e = g_off[w + 1];
    for (int j = s; j < e; j++) {
        int sr = g_csr[j];
        float nw = g_dinv0[sr] * dvi;
        a0 += g_xw0[sr * 64 + lane] * nw;
        a1 += g_xw0[sr * 64 + 32 + lane] * nw;
    }
    a0 = fmaxf(a0 + b1[lane], 0.f);
    a1 = fmaxf(a1 + b1[32 + lane], 0.f);
    g_h1[w * 64 + lane] = a0;
    g_h1[w * 64 + 32 + lane] = a1;
    float p = a0 * Wp[lane] + a1 * Wp[32 + lane];
    #pragma unroll
    for (int off = 16; off >= 1; off >>= 1) p += __shfl_xor_sync(0xffffffffu, p, off);
    if (lane == 0) g_s0w[w] = p;
}

// score for graph 0 (scalar GCN over same adjacency), one warp per node
__global__ void k_score0(const float* __restrict__ bp) {
    int w = (blockIdx.x * blockDim.x + threadIdx.x) >> 5;
    int lane = threadIdx.x & 31;
    if (w >= N_NODES) return;
    float part = 0.f;
    int s = g_off[w], e = g_off[w + 1];
    for (int j = s + lane; j < e; j += 32) {
        int sr = g_csr[j];
        part += g_s0w[sr] * g_dinv0[sr];
    }
    #pragma unroll
    for (int off = 16; off >= 1; off >>= 1) part += __shfl_xor_sync(0xffffffffu, part, off);
    if (lane == 0) {
        float dvi = g_dinv0[w];
        g_score[w] = bp[0] + g_s0w[w] * dvi * dvi + dvi * part;
    }
}

// scores for graphs 1..63: score = relu(x@W1+b1) @ Wp + bp, fully fused per node
__global__ void k_score_rest(const float* __restrict__ data, const float* __restrict__ W1,
                             const float* __restrict__ b1, const float* __restrict__ Wp,
                             const float* __restrict__ bp) {
    __shared__ float W1s[FIN * H1DIM];
    __shared__ float b1s[H1DIM];
    __shared__ float Wps[H1DIM];
    int tid = threadIdx.x;
    for (int i = tid; i < FIN * H1DIM; i += 256) W1s[i] = W1[i];
    for (int i = tid; i < H1DIM; i += 256) { b1s[i] = b1[i]; Wps[i] = Wp[i]; }
    __syncthreads();
    int gid = blockIdx.x * blockDim.x + tid;
    if (gid >= 63 * N_NODES) return;
    int n = N_NODES + gid;
    const float* xr = data + (long long)n * FIN;
    float x0 = xr[0], x1 = xr[1], x2 = xr[2], x3 = xr[3], x4 = xr[4], x5 = xr[5];
    float acc = bp[0];
    #pragma unroll 8
    for (int c = 0; c < H1DIM; c++) {
        float v = x0 * W1s[c] + x1 * W1s[64 + c] + x2 * W1s[128 + c] +
                  x3 * W1s[192 + c] + x4 * W1s[256 + c] + x5 * W1s[320 + c] + b1s[c];
        acc += fmaxf(v, 0.f) * Wps[c];
    }
    g_score[n] = acc;
}

// per-graph radix top-K select -> kept mask (lowest-index tie break)
__global__ void k_select() {
    int b = blockIdx.x;
    const float* sc = g_score + (long long)b * N_NODES;
    __shared__ int hist[256];
    __shared__ unsigned sh_pref;
    __shared__ int sh_need;
    __shared__ int eqn;
    __shared__ int eql[4096];
    int tid = threadIdx.x;
    unsigned prefix = 0;
    int need = KTOP;
    for (int shift = 24; shift >= 0; shift -= 8) {
        for (int i = tid; i < 256; i += blockDim.x) hist[i] = 0;
        __syncthreads();
        for (int i = tid; i < N_NODES; i += blockDim.x) {
            unsigned u = okey(sc[i]);
            if (shift == 24 || (u >> (shift + 8)) == prefix)
                atomicAdd(&hist[(u >> shift) & 255], 1);
        }
        __syncthreads();
        if (tid == 0) {
            int cum = 0, sel = 0;
            for (int v = 255; v >= 0; v--) {
                int h = hist[v];
                if (cum + h >= need) { sel = v; break; }
                cum += h;
            }
            sh_pref = (prefix << 8) | (unsigned)sel;
            sh_need = need - cum;
        }
        __syncthreads();
        prefix = sh_pref;
        need = sh_need;
        __syncthreads();
    }
    unsigned tau = prefix;
    if (tid == 0) eqn = 0;
    __syncthreads();
    for (int i = tid; i < N_NODES; i += blockDim.x) {
        unsigned u = okey(sc[i]);
        g_kept[(long long)b * N_NODES + i] = (u > tau) ? 1 : 0;
        if (u == tau) {
            int p = atomicAdd(&eqn, 1);
            if (p < 4096) eql[p] = i;
        }
    }
    __syncthreads();
    int ne = min(eqn, 4096);
    for (int t = tid; t < ne; t += blockDim.x) {
        int idx = eql[t];
        int rank = 0;
        for (int j = 0; j < ne; j++) rank += (eql[j] < idx);
        if (rank < need) g_kept[(long long)b * N_NODES + idx] = 1;
    }
}

// graph 0: xpw = tanh(score)*(h1 @ W2); zero for dropped nodes
__global__ void k_xpw0(const float* __restrict__ W2) {
    __shared__ __align__(16) float W2s[H1DIM * H2DIM];
    int tid = threadIdx.x;
    for (int i = tid; i < H1DIM * H2DIM; i += 256) W2s[i] = W2[i];
    __syncthreads();
    int n = blockIdx.x * blockDim.x + tid;
    if (n >= N_NODES) return;
    float t = g_kept[n] ? tanhf(g_score[n]) : 0.f;
    float acc[H2DIM];
    #pragma unroll
    for (int c = 0; c < H2DIM; c++) acc[c] = 0.f;
    #pragma unroll 4
    for (int k = 0; k < H1DIM; k++) {
        float h = g_h1[n * H1DIM + k];
        const float4* w4 = (const float4*)(W2s + k * H2DIM);
        #pragma unroll
        for (int c4 = 0; c4 < 8; c4++) {
            float4 w = w4[c4];
            acc[c4 * 4 + 0] += h * w.x;
            acc[c4 * 4 + 1] += h * w.y;
            acc[c4 * 4 + 2] += h * w.z;
            acc[c4 * 4 + 3] += h * w.w;
        }
    }
    #pragma unroll
    for (int c = 0; c < H2DIM; c++) g_xpw[n * H2DIM + c] = t * acc[c];
}

// deg2 / dinv2 over surviving subgraph (dinv2=0 for dropped -> free edge mask)
__global__ void k_deg2() {
    int n = blockIdx.x * blockDim.x + threadIdx.x;
    if (n >= N_NODES) return;
    if (g_kept[n]) {
        int cnt = 0;
        int s = g_off[n], e = g_off[n + 1];
        for (int j = s; j < e; j++) cnt += g_kept[g_csr[j]];
        g_dinv2[n] = rsqrtf(1.0f + (float)cnt);
    } else {
        g_dinv2[n] = 0.f;
    }
}

// graph 0 conv2 + relu + max-pool into g_gmax[0..31]; one warp per node, lane = channel
__global__ void k_h2_0(const float* __restrict__ b2) {
    __shared__ int smax[H2DIM];
    int tid = threadIdx.x;
    if (tid < H2DIM) smax[tid] = 0;
    __syncthreads();
    int w = blockIdx.x * 8 + (tid >> 5);
    int lane = tid & 31;
    float v = 0.f;
    if (w < N_NODES && g_kept[w]) {
        float dvi = g_dinv2[w];
        float acc = g_xpw[w * H2DIM + lane] * dvi * dvi;
        int s = g_off[w], e = g_off[w + 1];
        for (int j = s; j < e; j++) {
            int sr = g_csr[j];
            acc += g_xpw[sr * H2DIM + lane] * (g_dinv2[sr] * dvi);
        }
        v = fmaxf(acc + b2[lane], 0.f);
    }
    atomicMax(&smax[lane], __float_as_int(v));
    __syncthreads();
    if (tid < H2DIM)
        atomicMax(reinterpret_cast<int*>(&g_gmax[tid]), smax[tid]);
}

// graphs 1..63: fused h1 recompute -> h2 -> relu -> per-graph max-pool
__global__ void k_rest(const float* __restrict__ data, const float* __restrict__ W1,
                       const float* __restrict__ b1, const float* __restrict__ W2,
                       const float* __restrict__ b2) {
    __shared__ float W1s[FIN * H1DIM];
    __shared__ float b1s[H1DIM];
    __shared__ __align__(16) float W2s[H1DIM * H2DIM];
    __shared__ float b2s[H2DIM];
    __shared__ int smax[H2DIM];
    int tid = threadIdx.x;
    for (int i = tid; i < FIN * H1DIM; i += 256) W1s[i] = W1[i];
    for (int i = tid; i < H1DIM; i += 256) b1s[i] = b1[i];
    for (int i = tid; i < H1DIM * H2DIM; i += 256) W2s[i] = W2[i];
    if (tid < H2DIM) { b2s[tid] = b2[tid]; smax[tid] = 0; }
    __syncthreads();

    int nig = blockIdx.x * blockDim.x + tid;
    int bg = blockIdx.y + 1;
    bool valid = nig < N_NODES;
    int n = bg * N_NODES + (valid ? nig : 0);
    bool kp = valid && g_kept[n];

    float v[H2DIM];
    #pragma unroll
    for (int c = 0; c < H2DIM; c++) v[c] = 0.f;

    if (__ballot_sync(0xffffffffu, kp)) {
        float t = kp ? tanhf(g_score[n]) : 0.f;
        const float* xr = data + (long long)n * FIN;
        float x0 = xr[0], x1 = xr[1], x2 = xr[2], x3 = xr[3], x4 = xr[4], x5 = xr[5];
        float acc[H2DIM];
        #pragma unroll
        for (int c = 0; c < H2DIM; c++) acc[c] = 0.f;
        #pragma unroll 4
        for (int k = 0; k < H1DIM; k++) {
            float h = x0 * W1s[k] + x1 * W1s[64 + k] + x2 * W1s[128 + k] +
                      x3 * W1s[192 + k] + x4 * W1s[256 + k] + x5 * W1s[320 + k] + b1s[k];
            h = fmaxf(h, 0.f);
            const float4* w4 = (const float4*)(W2s + k * H2DIM);
            #pragma unroll
            for (int c4 = 0; c4 < 8; c4++) {
                float4 w = w4[c4];
                acc[c4 * 4 + 0] += h * w.x;
                acc[c4 * 4 + 1] += h * w.y;
                acc[c4 * 4 + 2] += h * w.z;
                acc[c4 * 4 + 3] += h * w.w;
            }
        }
        if (kp) {
            #pragma unroll
            for (int c = 0; c < H2DIM; c++) v[c] = fmaxf(t * acc[c] + b2s[c], 0.f);
        }
    }

    int lane = tid & 31;
    #pragma unroll
    for (int c = 0; c < H2DIM; c++) {
        float m = v[c];
        m = fmaxf(m, __shfl_xor_sync(0xffffffffu, m, 16));
        m = fmaxf(m, __shfl_xor_sync(0xffffffffu, m, 8));
        m = fmaxf(m, __shfl_xor_sync(0xffffffffu, m, 4));
        m = fmaxf(m, __shfl_xor_sync(0xffffffffu, m, 2));
        m = fmaxf(m, __shfl_xor_sync(0xffffffffu, m, 1));
        if (lane == 0) atomicMax(&smax[c], __float_as_int(m));
    }
    __syncthreads();
    if (tid < H2DIM)
        atomicMax(reinterpret_cast<int*>(&g_gmax[bg * H2DIM + tid]), smax[tid]);
}

__global__ void k_final(const float* __restrict__ Wf, const float* __restrict__ bf,
                        float* __restrict__ out) {
    int b = threadIdx.x;
    if (b >= BATCH) return;
    float acc = bf[0];
    #pragma unroll
    for (int c = 0; c < H2DIM; c++) acc += g_gmax[b * H2DIM + c] * Wf[c];
    out[b] = 1.f / (1.f + expf(-acc));
}

// ---------------- launch ----------------
extern "C" void kernel_launch(void* const* d_in, const int* in_sizes, int n_in,
                              void* d_out, int out_size) {
    const float* data = (const float*)d_in[0];
    const void*  ei   = d_in[1];
    const float* W1   = (const float*)d_in[2];
    const float* b1   = (const float*)d_in[3];
    const float* Wp   = (const float*)d_in[4];
    const float* bp   = (const float*)d_in[5];
    const float* W2   = (const float*)d_in[6];
    const float* b2   = (const float*)d_in[7];
    const float* Wf   = (const float*)d_in[8];
    const float* bf   = (const float*)d_in[9];
    float* out = (float*)d_out;

    k_zero<<<(N_NODES + 255) / 256, 256>>>();
    k_detect<<<1, 1>>>(ei);
    k_count<<<(NEDGE + 255) / 256, 256>>>(ei);
    k_scan<<<1, 1024>>>();
    k_scatter<<<(NEDGE + 255) / 256, 256>>>(ei);
    k_xw0<<<(N_NODES + 3) / 4, dim3(64, 4)>>>(data, W1);
    k_h1<<<(N_NODES + 7) / 8, 256>>>(b1, Wp);
    k_score0<<<(N_NODES + 7) / 8, 256>>>(bp);
    k_score_rest<<<(63 * N_NODES + 255) / 256, 256>>>(data, W1, b1, Wp, bp);
    k_select<<<BATCH, 256>>>();
    k_xpw0<<<(N_NODES + 255) / 256, 256>>>(W2);
    k_deg2<<<(N_NODES + 255) / 256, 256>>>();
    k_h2_0<<<(N_NODES + 7) / 8, 256>>>(b2);
    k_rest<<<dim3((N_NODES + 255) / 256, 63), 256>>>(data, W1, b1, W2, b2);
    k_final<<<1, 64>>>(Wf, bf, out);
}

// round 2
// speedup vs baseline: 1.2590x; 1.2590x over previous
#include <cuda_runtime.h>
#include <cuda_bf16.h>

#define N_NODES 17186
#define KTOP    12031
#define BATCH   64
#define NEDGE   500000
#define NTOT    (BATCH * N_NODES)
#define FIN     6
#define H1DIM   64
#define H2DIM   32
#define NSCANB  ((N_NODES + 1023) / 1024)   // 17

typedef unsigned long long ull;

// ---------------- device scratch (static, no allocations) ----------------
__device__ int   g_is64;
__device__ int   g_degcnt[N_NODES];
__device__ int   g_off[N_NODES + 1];
__device__ int   g_cursor[N_NODES];
__device__ int   g_csr[NEDGE];
__device__ int   g_blksum[32];
__device__ float g_dinv0[N_NODES];
__device__ float g_xw0[N_NODES * H1DIM];   // x@W1, interleaved: [n][lane*2 + half]
__device__ float g_h1[N_NODES * H1DIM];    // relu(gcn1), standard layout [n][c]
__device__ float g_s0w[N_NODES];           // h1 @ Wp, graph 0
__device__ float g_score[NTOT];
__device__ unsigned char g_kept[NTOT];
__device__ float g_dinv2[N_NODES];
__device__ float g_xpw[N_NODES * H2DIM];   // tanh(score)*(h1@W2) for graph 0
__device__ float g_gmax[BATCH * H2DIM];

// ---------------- helpers ----------------
__device__ __forceinline__ int eidx(const void* ei, long long pos) {
    if (g_is64) return (int)((const long long*)ei)[pos];
    return ((const int*)ei)[pos];
}

__device__ __forceinline__ unsigned okey(float f) {
    unsigned u = __float_as_uint(f);
    u ^= (u & 0x80000000u) ? 0xFFFFFFFFu : 0x80000000u;
    return u;
}

__device__ __forceinline__ ull pack2(float lo, float hi) {
    ull r; asm("mov.b64 %0, {%1, %2};" : "=l"(r) : "f"(lo), "f"(hi)); return r;
}
__device__ __forceinline__ void unpack2(ull v, float& lo, float& hi) {
    asm("mov.b64 {%0, %1}, %2;" : "=f"(lo), "=f"(hi) : "l"(v));
}
__device__ __forceinline__ void ffma2(ull& d, ull a, ull b) {
    asm("fma.rn.f32x2 %0, %1, %2, %0;" : "+l"(d) : "l"(a), "l"(b));
}

// ---------------- setup kernels ----------------
__global__ void k_zero(const void* ei) {
    int i = blockIdx.x * blockDim.x + threadIdx.x;
    if (i < N_NODES) { g_degcnt[i] = 0; g_cursor[i] = 0; }
    if (i < BATCH * H2DIM) g_gmax[i] = 0.f;
    if (i == 0) {
        const long long* p = (const long long*)ei;
        int ok = 1;
        for (int j = 0; j < 8; j++) {
            long long v = p[j];
            if (v < 0 || v >= N_NODES) ok = 0;
        }
        g_is64 = ok;
    }
}

__global__ void k_count(const void* ei) {
    int e = blockIdx.x * blockDim.x + threadIdx.x;
    if (e < NEDGE) {
        int d = eidx(ei, (long long)NEDGE + e);
        atomicAdd(&g_degcnt[d], 1);
    }
}

// parallel scan, stage 1: per-block local exclusive scan + block sums + dinv0
__global__ void k_scan1() {
    __shared__ int sh[1024];
    int tid = threadIdx.x;
    int idx = blockIdx.x * 1024 + tid;
    int v = (idx < N_NODES) ? g_degcnt[idx] : 0;
    if (idx < N_NODES) g_dinv0[idx] = rsqrtf(1.0f + (float)v);
    sh[tid] = v;
    __syncthreads();
    for (int off = 1; off < 1024; off <<= 1) {
        int t = (tid >= off) ? sh[tid - off] : 0;
        __syncthreads();
        sh[tid] += t;
        __syncthreads();
    }
    if (idx < N_NODES) g_off[idx] = sh[tid] - v;
    if (tid == 1023) g_blksum[blockIdx.x] = sh[1023];
}

// stage 2: warp-scan the block sums (NSCANB <= 32)
__global__ void k_scan2() {
    int tid = threadIdx.x;
    int v = (tid < NSCANB) ? g_blksum[tid] : 0;
    int inc = v;
    #pragma unroll
    for (int off = 1; off < 32; off <<= 1) {
        int t = __shfl_up_sync(0xffffffffu, inc, off);
        if (tid >= off) inc += t;
    }
    if (tid < NSCANB) g_blksum[tid] = inc - v;
    if (tid == NSCANB - 1) g_off[N_NODES] = inc;
}

// stage 3: add block prefixes
__global__ void k_scan3() {
    int idx = blockIdx.x * 1024 + threadIdx.x;
    if (idx < N_NODES) g_off[idx] += g_blksum[blockIdx.x];
}

__global__ void k_scatter(const void* ei) {
    int e = blockIdx.x * blockDim.x + threadIdx.x;
    if (e < NEDGE) {
        int d = eidx(ei, (long long)NEDGE + e);
        int s = eidx(ei, e);
        int pos = g_off[d] + atomicAdd(&g_cursor[d], 1);
        g_csr[pos] = s;
    }
}

// xw0 = x(graph0) @ W1 (raw, no bias), interleaved layout [n][lane*2 + (c>>5)]
__global__ void k_xw0(const float* __restrict__ data, const float* __restrict__ W1) {
    __shared__ float W1s[FIN * H1DIM];
    __shared__ float xs[4][8];
    int t = threadIdx.y * 64 + threadIdx.x;
    for (int i = t; i < FIN * H1DIM; i += 256) W1s[i] = W1[i];
    int node = blockIdx.x * 4 + threadIdx.y;
    if (threadIdx.x < FIN && node < N_NODES)
        xs[threadIdx.y][threadIdx.x] = data[node * FIN + threadIdx.x];
    __syncthreads();
    if (node < N_NODES) {
        int c = threadIdx.x;
        float acc = 0.f;
        #pragma unroll
        for (int k = 0; k < FIN; k++) acc += xs[threadIdx.y][k] * W1s[k * H1DIM + c];
        g_xw0[node * 64 + ((c & 31) * 2 + (c >> 5))] = acc;
    }
}

// h1 = relu(msg + self + b1); also s0w = h1 @ Wp  (one warp per node)
__global__ void k_h1(const float* __restrict__ b1, const float* __restrict__ Wp) {
    int w = (blockIdx.x * blockDim.x + threadIdx.x) >> 5;
    int lane = threadIdx.x & 31;
    if (w >= N_NODES) return;
    float dvi = g_dinv0[w];
    float selfw = dvi * dvi;
    float2 xw = *(const float2*)(g_xw0 + w * 64 + lane * 2);
    float a0 = xw.x * selfw;
    float a1 = xw.y * selfw;
    int s = g_off[w], e = g_off[w + 1];
    for (int j = s; j < e; j++) {
        int sr = g_csr[j];
        float nw = g_dinv0[sr] * dvi;
        float2 m = *(const float2*)(g_xw0 + sr * 64 + lane * 2);
        a0 += m.x * nw;
        a1 += m.y * nw;
    }
    a0 = fmaxf(a0 + b1[lane], 0.f);
    a1 = fmaxf(a1 + b1[32 + lane], 0.f);
    g_h1[w * 64 + lane] = a0;
    g_h1[w * 64 + 32 + lane] = a1;
    float p = a0 * Wp[lane] + a1 * Wp[32 + lane];
    #pragma unroll
    for (int off = 16; off >= 1; off >>= 1) p += __shfl_xor_sync(0xffffffffu, p, off);
    if (lane == 0) g_s0w[w] = p;
}

// score for graph 0 (scalar GCN over same adjacency), one warp per node
__global__ void k_score0(const float* __restrict__ bp) {
    int w = (blockIdx.x * blockDim.x + threadIdx.x) >> 5;
    int lane = threadIdx.x & 31;
    if (w >= N_NODES) return;
    float part = 0.f;
    int s = g_off[w], e = g_off[w + 1];
    for (int j = s + lane; j < e; j += 32) {
        int sr = g_csr[j];
        part += g_s0w[sr] * g_dinv0[sr];
    }
    #pragma unroll
    for (int off = 16; off >= 1; off >>= 1) part += __shfl_xor_sync(0xffffffffu, part, off);
    if (lane == 0) {
        float dvi = g_dinv0[w];
        g_score[w] = bp[0] + g_s0w[w] * dvi * dvi + dvi * part;
    }
}

// scores for graphs 1..63: score = relu(x@W1+b1) @ Wp + bp, packed f32x2
__global__ void k_score_rest(const float* __restrict__ data, const float* __restrict__ W1,
                             const float* __restrict__ b1, const float* __restrict__ Wp,
                             const float* __restrict__ bp) {
    __shared__ __align__(16) float W1s[FIN * H1DIM];   // [f*64 + c]
    __shared__ __align__(16) float b1s[H1DIM];
    __shared__ __align__(16) float Wps[H1DIM];
    int tid = threadIdx.x;
    for (int i = tid; i < FIN * H1DIM; i += 256) W1s[i] = W1[i];
    for (int i = tid; i < H1DIM; i += 256) { b1s[i] = b1[i]; Wps[i] = Wp[i]; }
    __syncthreads();
    int gid = blockIdx.x * blockDim.x + tid;
    if (gid >= 63 * N_NODES) return;
    int n = N_NODES + gid;
    const float* xr = data + (long long)n * FIN;
    float x0 = xr[0], x1 = xr[1], x2 = xr[2], x3 = xr[3], x4 = xr[4], x5 = xr[5];
    ull xb[6];
    xb[0] = pack2(x0, x0); xb[1] = pack2(x1, x1); xb[2] = pack2(x2, x2);
    xb[3] = pack2(x3, x3); xb[4] = pack2(x4, x4); xb[5] = pack2(x5, x5);
    const ull* W1p = reinterpret_cast<const ull*>(W1s);
    const ull* b1p = reinterpret_cast<const ull*>(b1s);
    const ull* Wpp = reinterpret_cast<const ull*>(Wps);
    ull acc2 = 0;
    #pragma unroll 4
    for (int c2 = 0; c2 < 32; c2++) {
        ull h2 = b1p[c2];
        #pragma unroll
        for (int f = 0; f < FIN; f++) ffma2(h2, xb[f], W1p[f * 32 + c2]);
        float h0, h1; unpack2(h2, h0, h1);
        h0 = fmaxf(h0, 0.f); h1 = fmaxf(h1, 0.f);
        ull hr = pack2(h0, h1);
        ffma2(acc2, hr, Wpp[c2]);
    }
    float a0, a1; unpack2(acc2, a0, a1);
    g_score[n] = a0 + a1 + bp[0];
}

// per-graph radix top-K select -> kept mask (lowest-index tie break)
__global__ void k_select() {
    int b = blockIdx.x;
    const float* sc = g_score + (long long)b * N_NODES;
    __shared__ int hist[256];
    __shared__ unsigned sh_pref;
    __shared__ int sh_need;
    __shared__ int eqn;
    __shared__ int eql[4096];
    int tid = threadIdx.x;
    unsigned prefix = 0;
    int need = KTOP;
    for (int shift = 24; shift >= 0; shift -= 8) {
        for (int i = tid; i < 256; i += blockDim.x) hist[i] = 0;
        __syncthreads();
        for (int i = tid; i < N_NODES; i += blockDim.x) {
            unsigned u = okey(sc[i]);
            if (shift == 24 || (u >> (shift + 8)) == prefix)
                atomicAdd(&hist[(u >> shift) & 255], 1);
        }
        __syncthreads();
        if (tid == 0) {
            int cum = 0, sel = 0;
            for (int v = 255; v >= 0; v--) {
                int h = hist[v];
                if (cum + h >= need) { sel = v; break; }
                cum += h;
            }
            sh_pref = (prefix << 8) | (unsigned)sel;
            sh_need = need - cum;
        }
        __syncthreads();
        prefix = sh_pref;
        need = sh_need;
        __syncthreads();
    }
    unsigned tau = prefix;
    if (tid == 0) eqn = 0;
    __syncthreads();
    for (int i = tid; i < N_NODES; i += blockDim.x) {
        unsigned u = okey(sc[i]);
        g_kept[(long long)b * N_NODES + i] = (u > tau) ? 1 : 0;
        if (u == tau) {
            int p = atomicAdd(&eqn, 1);
            if (p < 4096) eql[p] = i;
        }
    }
    __syncthreads();
    int ne = min(eqn, 4096);
    for (int t = tid; t < ne; t += blockDim.x) {
        int idx = eql[t];
        int rank = 0;
        for (int j = 0; j < ne; j++) rank += (eql[j] < idx);
        if (rank < need) g_kept[(long long)b * N_NODES + idx] = 1;
    }
}

// graph 0: xpw = tanh(score)*(h1 @ W2); only kept nodes matter (dinv2=0 elsewhere)
__global__ void k_xpw0(const float* __restrict__ W2) {
    __shared__ __align__(16) float W2s[H1DIM * H2DIM];
    int tid = threadIdx.x;
    for (int i = tid; i < H1DIM * H2DIM; i += 256) W2s[i] = W2[i];
    __syncthreads();
    int n = blockIdx.x * blockDim.x + tid;
    if (n >= N_NODES) return;
    if (!g_kept[n]) {
        // dinv2 will be 0 for this node; its xpw is never used with nonzero weight,
        // but keep it zero for determinism.
        #pragma unroll
        for (int c = 0; c < H2DIM; c++) g_xpw[n * H2DIM + c] = 0.f;
        return;
    }
    float t = tanhf(g_score[n]);
    const ull* W2p = reinterpret_cast<const ull*>(W2s);
    ull acc2[16];
    #pragma unroll
    for (int c2 = 0; c2 < 16; c2++) acc2[c2] = 0;
    const float4* hr = (const float4*)(g_h1 + n * H1DIM);
    #pragma unroll 4
    for (int k4 = 0; k4 < 16; k4++) {
        float4 h4 = hr[k4];
        ull hb0 = pack2(h4.x, h4.x), hb1 = pack2(h4.y, h4.y);
        ull hb2 = pack2(h4.z, h4.z), hb3 = pack2(h4.w, h4.w);
        const ull* w = W2p + (k4 * 4) * 16;
        #pragma unroll
        for (int c2 = 0; c2 < 16; c2++) {
            ffma2(acc2[c2], hb0, w[c2]);
            ffma2(acc2[c2], hb1, w[16 + c2]);
            ffma2(acc2[c2], hb2, w[32 + c2]);
            ffma2(acc2[c2], hb3, w[48 + c2]);
        }
    }
    #pragma unroll
    for (int c2 = 0; c2 < 16; c2++) {
        float lo, hi; unpack2(acc2[c2], lo, hi);
        g_xpw[n * H2DIM + 2 * c2] = t * lo;
        g_xpw[n * H2DIM + 2 * c2 + 1] = t * hi;
    }
}

// deg2 / dinv2 over surviving subgraph (dinv2=0 for dropped -> free edge mask)
__global__ void k_deg2() {
    int n = blockIdx.x * blockDim.x + threadIdx.x;
    if (n >= N_NODES) return;
    if (g_kept[n]) {
        int cnt = 0;
        int s = g_off[n], e = g_off[n + 1];
        for (int j = s; j < e; j++) cnt += g_kept[g_csr[j]];
        g_dinv2[n] = rsqrtf(1.0f + (float)cnt);
    } else {
        g_dinv2[n] = 0.f;
    }
}

// graph 0 conv2 + relu + max-pool into g_gmax[0..31]; one warp per node, lane = channel
__global__ void k_h2_0(const float* __restrict__ b2) {
    __shared__ int smax[H2DIM];
    int tid = threadIdx.x;
    if (tid < H2DIM) smax[tid] = 0;
    __syncthreads();
    int w = blockIdx.x * 8 + (tid >> 5);
    int lane = tid & 31;
    float v = 0.f;
    if (w < N_NODES && g_kept[w]) {
        float dvi = g_dinv2[w];
        float acc = g_xpw[w * H2DIM + lane] * dvi * dvi;
        int s = g_off[w], e = g_off[w + 1];
        for (int j = s; j < e; j++) {
            int sr = g_csr[j];
            acc += g_xpw[sr * H2DIM + lane] * (g_dinv2[sr] * dvi);
        }
        v = fmaxf(acc + b2[lane], 0.f);
    }
    atomicMax(&smax[lane], __float_as_int(v));
    __syncthreads();
    if (tid < H2DIM)
        atomicMax(reinterpret_cast<int*>(&g_gmax[tid]), smax[tid]);
}

// graphs 1..63: fused h1 recompute -> h2 -> relu -> per-graph max-pool (f32x2)
__global__ void k_rest(const float* __restrict__ data, const float* __restrict__ W1,
                       const float* __restrict__ b1, const float* __restrict__ W2,
                       const float* __restrict__ b2) {
    __shared__ __align__(16) float W1s[FIN * H1DIM];   // [f*64 + k]
    __shared__ __align__(16) float b1s[H1DIM];
    __shared__ __align__(16) float W2s[H1DIM * H2DIM]; // [k*32 + c]
    __shared__ __align__(16) float b2s[H2DIM];
    __shared__ int smax[H2DIM];
    int tid = threadIdx.x;
    for (int i = tid; i < FIN * H1DIM; i += 256) W1s[i] = W1[i];
    for (int i = tid; i < H1DIM; i += 256) b1s[i] = b1[i];
    for (int i = tid; i < H1DIM * H2DIM; i += 256) W2s[i] = W2[i];
    if (tid < H2DIM) { b2s[tid] = b2[tid]; smax[tid] = 0; }
    __syncthreads();

    int nig = blockIdx.x * blockDim.x + tid;
    int bg = blockIdx.y + 1;
    bool valid = nig < N_NODES;
    int n = bg * N_NODES + (valid ? nig : 0);
    bool kp = valid && g_kept[n];

    ull acc2[16];
    #pragma unroll
    for (int c2 = 0; c2 < 16; c2++) acc2[c2] = 0;
    float t = 0.f;

    if (__ballot_sync(0xffffffffu, kp)) {
        if (kp) t = tanhf(g_score[n]);
        const float* xr = data + (long long)n * FIN;
        ull xb[6];
        #pragma unroll
        for (int f = 0; f < FIN; f++) { float x = xr[f]; xb[f] = pack2(x, x); }
        const ull* W1p = reinterpret_cast<const ull*>(W1s);  // [f*32 + k2]
        const ull* b1p = reinterpret_cast<const ull*>(b1s);
        const ull* W2p = reinterpret_cast<const ull*>(W2s);  // [k*16 + c2]
        #pragma unroll 4
        for (int k2 = 0; k2 < 32; k2++) {
            ull h2 = b1p[k2];
            #pragma unroll
            for (int f = 0; f < FIN; f++) ffma2(h2, xb[f], W1p[f * 32 + k2]);
            float h0, h1; unpack2(h2, h0, h1);
            h0 = fmaxf(h0, 0.f); h1 = fmaxf(h1, 0.f);
            ull hb0 = pack2(h0, h0), hb1 = pack2(h1, h1);
            const ull* w0 = W2p + (2 * k2) * 16;
            #pragma unroll
            for (int c2 = 0; c2 < 16; c2++) {
                ffma2(acc2[c2], hb0, w0[c2]);
                ffma2(acc2[c2], hb1, w0[16 + c2]);
            }
        }
    }

    int lane = tid & 31;
    #pragma unroll
    for (int c2 = 0; c2 < 16; c2++) {
        float lo, hi; unpack2(acc2[c2], lo, hi);
        float m0 = kp ? fmaxf(fmaf(t, lo, b2s[2 * c2]), 0.f) : 0.f;
        float m1 = kp ? fmaxf(fmaf(t, hi, b2s[2 * c2 + 1]), 0.f) : 0.f;
        #pragma unroll
        for (int off = 16; off >= 1; off >>= 1) {
            m0 = fmaxf(m0, __shfl_xor_sync(0xffffffffu, m0, off));
            m1 = fmaxf(m1, __shfl_xor_sync(0xffffffffu, m1, off));
        }
        if (lane == 0) {
            atomicMax(&smax[2 * c2], __float_as_int(m0));
            atomicMax(&smax[2 * c2 + 1], __float_as_int(m1));
        }
    }
    __syncthreads();
    if (tid < H2DIM)
        atomicMax(reinterpret_cast<int*>(&g_gmax[bg * H2DIM + tid]), smax[tid]);
}

__global__ void k_final(const float* __restrict__ Wf, const float* __restrict__ bf,
                        float* __restrict__ out) {
    int b = threadIdx.x;
    if (b >= BATCH) return;
    float acc = bf[0];
    #pragma unroll
    for (int c = 0; c < H2DIM; c++) acc += g_gmax[b * H2DIM + c] * Wf[c];
    out[b] = 1.f / (1.f + expf(-acc));
}

// ---------------- launch ----------------
extern "C" void kernel_launch(void* const* d_in, const int* in_sizes, int n_in,
                              void* d_out, int out_size) {
    const float* data = (const float*)d_in[0];
    const void*  ei   = d_in[1];
    const float* W1   = (const float*)d_in[2];
    const float* b1   = (const float*)d_in[3];
    const float* Wp   = (const float*)d_in[4];
    const float* bp   = (const float*)d_in[5];
    const float* W2   = (const float*)d_in[6];
    const float* b2   = (const float*)d_in[7];
    const float* Wf   = (const float*)d_in[8];
    const float* bf   = (const float*)d_in[9];
    float* out = (float*)d_out;

    k_zero<<<(N_NODES + 255) / 256, 256>>>(ei);
    k_count<<<(NEDGE + 255) / 256, 256>>>(ei);
    k_scan1<<<NSCANB, 1024>>>();
    k_scan2<<<1, 32>>>();
    k_scan3<<<NSCANB, 1024>>>();
    k_scatter<<<(NEDGE + 255) / 256, 256>>>(ei);
    k_xw0<<<(N_NODES + 3) / 4, dim3(64, 4)>>>(data, W1);
    k_h1<<<(N_NODES + 7) / 8, 256>>>(b1, Wp);
    k_score0<<<(N_NODES + 7) / 8, 256>>>(bp);
    k_score_rest<<<(63 * N_NODES + 255) / 256, 256>>>(data, W1, b1, Wp, bp);
    k_select<<<BATCH, 1024>>>();
    k_xpw0<<<(N_NODES + 255) / 256, 256>>>(W2);
    k_deg2<<<(N_NODES + 255) / 256, 256>>>();
    k_h2_0<<<(N_NODES + 7) / 8, 256>>>(b2);
    k_rest<<<dim3((N_NODES + 255) / 256, 63), 256>>>(data, W1, b1, W2, b2);
    k_final<<<1, 64>>>(Wf, bf, out);
}

// round 3
// speedup vs baseline: 1.5263x; 1.2123x over previous
#include <cuda_runtime.h>
#include <cuda_bf16.h>

#define N_NODES 17186
#define KTOP    12031
#define BATCH   64
#define NEDGE   500000
#define NTOT    (BATCH * N_NODES)
#define FIN     6
#define H1DIM   64
#define H2DIM   32
#define NSCANB  ((N_NODES + 1023) / 1024)   // 17

typedef unsigned long long ull;

// ---------------- device scratch (static, no allocations) ----------------
__device__ int   g_is64;
__device__ int   g_degcnt[N_NODES];
__device__ int   g_off[N_NODES + 1];
__device__ int   g_cursor[N_NODES];
__device__ int   g_csr[NEDGE];
__device__ int   g_blksum[32];
__device__ float g_dinv0[N_NODES];
__device__ float g_xw0[N_NODES * H1DIM];   // x@W1, interleaved: [n][lane*2 + half]
__device__ float g_h1[N_NODES * H1DIM];    // relu(gcn1), standard layout [n][c]
__device__ float g_s0w[N_NODES];           // h1 @ Wp, graph 0
__device__ float g_score[NTOT];
__device__ unsigned char g_kept[NTOT];
__device__ int   g_knum[BATCH];
__device__ int   g_kidx[63 * KTOP];        // compacted kept node-in-graph ids, graphs 1..63
__device__ float g_dinv2[N_NODES];
__device__ float g_xpw[N_NODES * H2DIM];   // tanh(score)*(h1@W2) for graph 0
__device__ float g_gmax[BATCH * H2DIM];

// ---------------- helpers ----------------
__device__ __forceinline__ int eidx(const void* ei, long long pos) {
    if (g_is64) return (int)((const long long*)ei)[pos];
    return ((const int*)ei)[pos];
}

__device__ __forceinline__ unsigned okey(float f) {
    unsigned u = __float_as_uint(f);
    u ^= (u & 0x80000000u) ? 0xFFFFFFFFu : 0x80000000u;
    return u;
}

__device__ __forceinline__ ull pack2(float lo, float hi) {
    ull r; asm("mov.b64 %0, {%1, %2};" : "=l"(r) : "f"(lo), "f"(hi)); return r;
}
__device__ __forceinline__ void unpack2(ull v, float& lo, float& hi) {
    asm("mov.b64 {%0, %1}, %2;" : "=f"(lo), "=f"(hi) : "l"(v));
}
__device__ __forceinline__ void ffma2(ull& d, ull a, ull b) {
    asm("fma.rn.f32x2 %0, %1, %2, %0;" : "+l"(d) : "l"(a), "l"(b));
}

// ---------------- setup kernels ----------------
__global__ void k_zero(const void* ei) {
    int i = blockIdx.x * blockDim.x + threadIdx.x;
    if (i < N_NODES) { g_degcnt[i] = 0; g_cursor[i] = 0; }
    if (i < BATCH * H2DIM) g_gmax[i] = 0.f;
    if (i < BATCH) g_knum[i] = 0;
    if (i == 0) {
        const long long* p = (const long long*)ei;
        int ok = 1;
        for (int j = 0; j < 8; j++) {
            long long v = p[j];
            if (v < 0 || v >= N_NODES) ok = 0;
        }
        g_is64 = ok;
    }
}

__global__ void k_count(const void* ei) {
    int e = blockIdx.x * blockDim.x + threadIdx.x;
    if (e < NEDGE) {
        int d = eidx(ei, (long long)NEDGE + e);
        atomicAdd(&g_degcnt[d], 1);
    }
}

// parallel scan, stage 1: per-block local exclusive scan + block sums + dinv0
__global__ void k_scan1() {
    __shared__ int sh[1024];
    int tid = threadIdx.x;
    int idx = blockIdx.x * 1024 + tid;
    int v = (idx < N_NODES) ? g_degcnt[idx] : 0;
    if (idx < N_NODES) g_dinv0[idx] = rsqrtf(1.0f + (float)v);
    sh[tid] = v;
    __syncthreads();
    for (int off = 1; off < 1024; off <<= 1) {
        int t = (tid >= off) ? sh[tid - off] : 0;
        __syncthreads();
        sh[tid] += t;
        __syncthreads();
    }
    if (idx < N_NODES) g_off[idx] = sh[tid] - v;
    if (tid == 1023) g_blksum[blockIdx.x] = sh[1023];
}

// stage 2: each block redundantly warp-scans the block sums, adds its prefix
__global__ void k_scan3() {
    __shared__ int sPrefix;
    int tid = threadIdx.x;
    if (tid < 32) {
        int v = (tid < NSCANB) ? g_blksum[tid] : 0;
        int inc = v;
        #pragma unroll
        for (int off = 1; off < 32; off <<= 1) {
            int t = __shfl_up_sync(0xffffffffu, inc, off);
            if (tid >= off) inc += t;
        }
        if (tid == (int)blockIdx.x) sPrefix = inc - v;
        if (blockIdx.x == 0 && tid == NSCANB - 1) g_off[N_NODES] = inc;
    }
    __syncthreads();
    int idx = blockIdx.x * 1024 + tid;
    if (idx < N_NODES) g_off[idx] += sPrefix;
}

__global__ void k_scatter(const void* ei) {
    int e = blockIdx.x * blockDim.x + threadIdx.x;
    if (e < NEDGE) {
        int d = eidx(ei, (long long)NEDGE + e);
        int s = eidx(ei, e);
        int pos = g_off[d] + atomicAdd(&g_cursor[d], 1);
        g_csr[pos] = s;
    }
}

// xw0 = x(graph0) @ W1 (raw, no bias), interleaved layout [n][lane*2 + (c>>5)]
__global__ void k_xw0(const float* __restrict__ data, const float* __restrict__ W1) {
    __shared__ float W1s[FIN * H1DIM];
    __shared__ float xs[4][8];
    int t = threadIdx.y * 64 + threadIdx.x;
    for (int i = t; i < FIN * H1DIM; i += 256) W1s[i] = W1[i];
    int node = blockIdx.x * 4 + threadIdx.y;
    if (threadIdx.x < FIN && node < N_NODES)
        xs[threadIdx.y][threadIdx.x] = data[node * FIN + threadIdx.x];
    __syncthreads();
    if (node < N_NODES) {
        int c = threadIdx.x;
        float acc = 0.f;
        #pragma unroll
        for (int k = 0; k < FIN; k++) acc += xs[threadIdx.y][k] * W1s[k * H1DIM + c];
        g_xw0[node * 64 + ((c & 31) * 2 + (c >> 5))] = acc;
    }
}

// h1 = relu(msg + self + b1); also s0w = h1 @ Wp  (one warp per node)
__global__ void k_h1(const float* __restrict__ b1, const float* __restrict__ Wp) {
    int w = (blockIdx.x * blockDim.x + threadIdx.x) >> 5;
    int lane = threadIdx.x & 31;
    if (w >= N_NODES) return;
    float dvi = g_dinv0[w];
    float selfw = dvi * dvi;
    float2 xw = *(const float2*)(g_xw0 + w * 64 + lane * 2);
    float a0 = xw.x * selfw;
    float a1 = xw.y * selfw;
    int s = g_off[w], e = g_off[w + 1];
    for (int j = s; j < e; j++) {
        int sr = g_csr[j];
        float nw = g_dinv0[sr] * dvi;
        float2 m = *(const float2*)(g_xw0 + sr * 64 + lane * 2);
        a0 += m.x * nw;
        a1 += m.y * nw;
    }
    a0 = fmaxf(a0 + b1[lane], 0.f);
    a1 = fmaxf(a1 + b1[32 + lane], 0.f);
    g_h1[w * 64 + lane] = a0;
    g_h1[w * 64 + 32 + lane] = a1;
    float p = a0 * Wp[lane] + a1 * Wp[32 + lane];
    #pragma unroll
    for (int off = 16; off >= 1; off >>= 1) p += __shfl_xor_sync(0xffffffffu, p, off);
    if (lane == 0) g_s0w[w] = p;
}

// score for graph 0 (scalar GCN over same adjacency), one warp per node
__global__ void k_score0(const float* __restrict__ bp) {
    int w = (blockIdx.x * blockDim.x + threadIdx.x) >> 5;
    int lane = threadIdx.x & 31;
    if (w >= N_NODES) return;
    float part = 0.f;
    int s = g_off[w], e = g_off[w + 1];
    for (int j = s + lane; j < e; j += 32) {
        int sr = g_csr[j];
        part += g_s0w[sr] * g_dinv0[sr];
    }
    #pragma unroll
    for (int off = 16; off >= 1; off >>= 1) part += __shfl_xor_sync(0xffffffffu, part, off);
    if (lane == 0) {
        float dvi = g_dinv0[w];
        g_score[w] = bp[0] + g_s0w[w] * dvi * dvi + dvi * part;
    }
}

// scores for graphs 1..63: score = relu(x@W1+b1) @ Wp + bp, packed f32x2
__global__ void k_score_rest(const float* __restrict__ data, const float* __restrict__ W1,
                             const float* __restrict__ b1, const float* __restrict__ Wp,
                             const float* __restrict__ bp) {
    __shared__ __align__(16) float W1s[FIN * H1DIM];
    __shared__ __align__(16) float b1s[H1DIM];
    __shared__ __align__(16) float Wps[H1DIM];
    int tid = threadIdx.x;
    for (int i = tid; i < FIN * H1DIM; i += 256) W1s[i] = W1[i];
    for (int i = tid; i < H1DIM; i += 256) { b1s[i] = b1[i]; Wps[i] = Wp[i]; }
    __syncthreads();
    int gid = blockIdx.x * blockDim.x + tid;
    if (gid >= 63 * N_NODES) return;
    int n = N_NODES + gid;
    const float* xr = data + (long long)n * FIN;
    ull xb[6];
    #pragma unroll
    for (int f = 0; f < FIN; f++) { float x = xr[f]; xb[f] = pack2(x, x); }
    const ull* W1p = reinterpret_cast<const ull*>(W1s);
    const ull* b1p = reinterpret_cast<const ull*>(b1s);
    const ull* Wpp = reinterpret_cast<const ull*>(Wps);
    ull acc2 = 0;
    #pragma unroll 4
    for (int c2 = 0; c2 < 32; c2++) {
        ull h2 = b1p[c2];
        #pragma unroll
        for (int f = 0; f < FIN; f++) ffma2(h2, xb[f], W1p[f * 32 + c2]);
        float h0, h1; unpack2(h2, h0, h1);
        h0 = fmaxf(h0, 0.f); h1 = fmaxf(h1, 0.f);
        ull hr = pack2(h0, h1);
        ffma2(acc2, hr, Wpp[c2]);
    }
    float a0, a1; unpack2(acc2, a0, a1);
    g_score[n] = a0 + a1 + bp[0];
}

// per-graph top-K: 3-pass radix (11/11/10 bits) with parallel suffix-scan selection
__global__ void k_select() {
    int b = blockIdx.x;
    const float* sc = g_score + (long long)b * N_NODES;
    __shared__ int hist[2048];
    __shared__ int wsum[32];
    __shared__ unsigned sh_pref;
    __shared__ int sh_need;
    __shared__ int eqn;
    __shared__ int eql[4096];
    int tid = threadIdx.x;
    int lane = tid & 31, wid = tid >> 5;
    unsigned prefix = 0;
    int need = KTOP;
    #pragma unroll
    for (int p = 0; p < 3; p++) {
        const int shift = (p == 0) ? 21 : (p == 1) ? 10 : 0;
        const int width = (p == 2) ? 10 : 11;
        hist[tid] = 0; hist[tid + 1024] = 0;
        __syncthreads();
        for (int i = tid; i < N_NODES; i += 1024) {
            unsigned u = okey(sc[i]);
            bool ok = (p == 0) || ((u >> (shift + width)) == prefix);
            if (ok) atomicAdd(&hist[(u >> shift) & ((1u << width) - 1u)], 1);
        }
        __syncthreads();
        // suffix-sum selection over bins (descending)
        int v0 = 2047 - 2 * tid, v1 = 2046 - 2 * tid;
        int h0 = hist[v0], h1 = hist[v1];
        int local = h0 + h1;
        int inc = local;
        #pragma unroll
        for (int o = 1; o < 32; o <<= 1) {
            int t2 = __shfl_up_sync(0xffffffffu, inc, o);
            if (lane >= o) inc += t2;
        }
        if (lane == 31) wsum[wid] = inc;
        __syncthreads();
        if (tid < 32) {
            int w = wsum[tid];
            int wi = w;
            #pragma unroll
            for (int o = 1; o < 32; o <<= 1) {
                int t2 = __shfl_up_sync(0xffffffffu, wi, o);
                if (tid >= o) wi += t2;
            }
            wsum[tid] = wi - w;
        }
        __syncthreads();
        int prevP = wsum[wid] + (inc - local);   // bins strictly above v0
        if (prevP < need && need <= prevP + h0) {
            sh_pref = (prefix << width) | (unsigned)v0;
            sh_need = need - prevP;
        } else if (prevP + h0 < need && need <= prevP + h0 + h1) {
            sh_pref = (prefix << width) | (unsigned)v1;
            sh_need = need - prevP - h0;
        }
        __syncthreads();
        prefix = sh_pref;
        need = sh_need;
        __syncthreads();
    }
    unsigned tau = prefix;
    if (tid == 0) eqn = 0;
    __syncthreads();
    for (int i = tid; i < N_NODES; i += 1024) {
        unsigned u = okey(sc[i]);
        g_kept[(long long)b * N_NODES + i] = (u > tau) ? 1 : 0;
        if (u == tau) {
            int p = atomicAdd(&eqn, 1);
            if (p < 4096) eql[p] = i;
        }
    }
    __syncthreads();
    int ne = min(eqn, 4096);
    for (int t = tid; t < ne; t += 1024) {
        int idx = eql[t];
        int rank = 0;
        for (int j = 0; j < ne; j++) rank += (eql[j] < idx);
        if (rank < need) g_kept[(long long)b * N_NODES + idx] = 1;
    }
}

// compact kept node ids for graphs 1..63 (order-free; max-pool is order-invariant)
__global__ void k_compact() {
    int nig = blockIdx.x * blockDim.x + threadIdx.x;
    int bg = blockIdx.y + 1;
    bool kp = (nig < N_NODES) && g_kept[bg * N_NODES + nig];
    unsigned mask = __ballot_sync(0xffffffffu, kp);
    if (!mask) return;
    int lane = threadIdx.x & 31;
    int leader = __ffs(mask) - 1;
    int base = 0;
    if (lane == leader) base = atomicAdd(&g_knum[bg], __popc(mask));
    base = __shfl_sync(0xffffffffu, base, leader);
    if (kp) {
        int pos = base + __popc(mask & ((1u << lane) - 1u));
        g_kidx[(bg - 1) * KTOP + pos] = nig;
    }
}

// graph 0: dinv2 + xpw = tanh(score)*(h1 @ W2) for kept nodes
__global__ void k_xpw0(const float* __restrict__ W2) {
    __shared__ __align__(16) float W2s[H1DIM * H2DIM];
    int tid = threadIdx.x;
    for (int i = tid; i < H1DIM * H2DIM; i += 256) W2s[i] = W2[i];
    __syncthreads();
    int n = blockIdx.x * blockDim.x + tid;
    if (n >= N_NODES) return;
    if (!g_kept[n]) {
        g_dinv2[n] = 0.f;
        #pragma unroll
        for (int c = 0; c < H2DIM; c++) g_xpw[n * H2DIM + c] = 0.f;
        return;
    }
    // dinv2 over surviving subgraph
    {
        int cnt = 0;
        int s = g_off[n], e = g_off[n + 1];
        for (int j = s; j < e; j++) cnt += g_kept[g_csr[j]];
        g_dinv2[n] = rsqrtf(1.0f + (float)cnt);
    }
    float t = tanhf(g_score[n]);
    const ull* W2p = reinterpret_cast<const ull*>(W2s);
    ull acc2[16];
    #pragma unroll
    for (int c2 = 0; c2 < 16; c2++) acc2[c2] = 0;
    const float4* hr = (const float4*)(g_h1 + n * H1DIM);
    #pragma unroll 4
    for (int k4 = 0; k4 < 16; k4++) {
        float4 h4 = hr[k4];
        ull hb0 = pack2(h4.x, h4.x), hb1 = pack2(h4.y, h4.y);
        ull hb2 = pack2(h4.z, h4.z), hb3 = pack2(h4.w, h4.w);
        const ull* w = W2p + (k4 * 4) * 16;
        #pragma unroll
        for (int c2 = 0; c2 < 16; c2++) {
            ffma2(acc2[c2], hb0, w[c2]);
            ffma2(acc2[c2], hb1, w[16 + c2]);
            ffma2(acc2[c2], hb2, w[32 + c2]);
            ffma2(acc2[c2], hb3, w[48 + c2]);
        }
    }
    #pragma unroll
    for (int c2 = 0; c2 < 16; c2++) {
        float lo, hi; unpack2(acc2[c2], lo, hi);
        g_xpw[n * H2DIM + 2 * c2] = t * lo;
        g_xpw[n * H2DIM + 2 * c2 + 1] = t * hi;
    }
}

// graph 0 conv2 + relu + max-pool into g_gmax[0..31]; one warp per node
__global__ void k_h2_0(const float* __restrict__ b2) {
    __shared__ int smax[H2DIM];
    int tid = threadIdx.x;
    if (tid < H2DIM) smax[tid] = 0;
    __syncthreads();
    int w = blockIdx.x * 8 + (tid >> 5);
    int lane = tid & 31;
    float v = 0.f;
    if (w < N_NODES && g_kept[w]) {
        float dvi = g_dinv2[w];
        float acc = g_xpw[w * H2DIM + lane] * dvi * dvi;
        int s = g_off[w], e = g_off[w + 1];
        for (int j = s; j < e; j++) {
            int sr = g_csr[j];
            acc += g_xpw[sr * H2DIM + lane] * (g_dinv2[sr] * dvi);
        }
        v = fmaxf(acc + b2[lane], 0.f);
    }
    atomicMax(&smax[lane], __float_as_int(v));
    __syncthreads();
    if (tid < H2DIM)
        atomicMax(reinterpret_cast<int*>(&g_gmax[tid]), smax[tid]);
}

// graphs 1..63 over compacted kept nodes: h1 recompute -> h2 -> relu -> max-pool
__global__ void k_rest(const float* __restrict__ data, const float* __restrict__ W1,
                       const float* __restrict__ b1, const float* __restrict__ W2,
                       const float* __restrict__ b2) {
    __shared__ __align__(16) float W1s[FIN * H1DIM];
    __shared__ __align__(16) float b1s[H1DIM];
    __shared__ __align__(16) float W2s[H1DIM * H2DIM];
    __shared__ __align__(16) float b2s[H2DIM];
    __shared__ int smax[H2DIM];
    int tid = threadIdx.x;
    for (int i = tid; i < FIN * H1DIM; i += 256) W1s[i] = W1[i];
    for (int i = tid; i < H1DIM; i += 256) b1s[i] = b1[i];
    for (int i = tid; i < H1DIM * H2DIM; i += 256) W2s[i] = W2[i];
    if (tid < H2DIM) { b2s[tid] = b2[tid]; smax[tid] = 0; }
    __syncthreads();

    int i = blockIdx.x * blockDim.x + tid;
    int bg = blockIdx.y + 1;
    bool valid = i < KTOP;
    int nig = valid ? g_kidx[(bg - 1) * KTOP + i] : 0;
    int n = bg * N_NODES + nig;
    float t = valid ? tanhf(g_score[n]) : 0.f;

    const float* xr = data + (long long)n * FIN;
    ull xb[6];
    #pragma unroll
    for (int f = 0; f < FIN; f++) { float x = xr[f]; xb[f] = pack2(x, x); }
    ull acc2[16];
    #pragma unroll
    for (int c2 = 0; c2 < 16; c2++) acc2[c2] = 0;
    const ull* W1p = reinterpret_cast<const ull*>(W1s);
    const ull* b1p = reinterpret_cast<const ull*>(b1s);
    const ull* W2p = reinterpret_cast<const ull*>(W2s);
    #pragma unroll 4
    for (int k2 = 0; k2 < 32; k2++) {
        ull h2 = b1p[k2];
        #pragma unroll
        for (int f = 0; f < FIN; f++) ffma2(h2, xb[f], W1p[f * 32 + k2]);
        float h0, h1; unpack2(h2, h0, h1);
        h0 = fmaxf(h0, 0.f); h1 = fmaxf(h1, 0.f);
        ull hb0 = pack2(h0, h0), hb1 = pack2(h1, h1);
        const ull* w0 = W2p + (2 * k2) * 16;
        #pragma unroll
        for (int c2 = 0; c2 < 16; c2++) {
            ffma2(acc2[c2], hb0, w0[c2]);
            ffma2(acc2[c2], hb1, w0[16 + c2]);
        }
    }

    int lane = tid & 31;
    #pragma unroll
    for (int c2 = 0; c2 < 16; c2++) {
        float lo, hi; unpack2(acc2[c2], lo, hi);
        float m0 = valid ? fmaxf(fmaf(t, lo, b2s[2 * c2]), 0.f) : 0.f;
        float m1 = valid ? fmaxf(fmaf(t, hi, b2s[2 * c2 + 1]), 0.f) : 0.f;
        #pragma unroll
        for (int off = 16; off >= 1; off >>= 1) {
            m0 = fmaxf(m0, __shfl_xor_sync(0xffffffffu, m0, off));
            m1 = fmaxf(m1, __shfl_xor_sync(0xffffffffu, m1, off));
        }
        if (lane == 0) {
            atomicMax(&smax[2 * c2], __float_as_int(m0));
            atomicMax(&smax[2 * c2 + 1], __float_as_int(m1));
        }
    }
    __syncthreads();
    if (tid < H2DIM)
        atomicMax(reinterpret_cast<int*>(&g_gmax[bg * H2DIM + tid]), smax[tid]);
}

__global__ void k_final(const float* __restrict__ Wf, const float* __restrict__ bf,
                        float* __restrict__ out) {
    int b = threadIdx.x;
    if (b >= BATCH) return;
    float acc = bf[0];
    #pragma unroll
    for (int c = 0; c < H2DIM; c++) acc += g_gmax[b * H2DIM + c] * Wf[c];
    out[b] = 1.f / (1.f + expf(-acc));
}

// ---------------- launch ----------------
extern "C" void kernel_launch(void* const* d_in, const int* in_sizes, int n_in,
                              void* d_out, int out_size) {
    const float* data = (const float*)d_in[0];
    const void*  ei   = d_in[1];
    const float* W1   = (const float*)d_in[2];
    const float* b1   = (const float*)d_in[3];
    const float* Wp   = (const float*)d_in[4];
    const float* bp   = (const float*)d_in[5];
    const float* W2   = (const float*)d_in[6];
    const float* b2   = (const float*)d_in[7];
    const float* Wf   = (const float*)d_in[8];
    const float* bf   = (const float*)d_in[9];
    float* out = (float*)d_out;

    k_zero<<<(N_NODES + 255) / 256, 256>>>(ei);
    k_count<<<(NEDGE + 255) / 256, 256>>>(ei);
    k_scan1<<<NSCANB, 1024>>>();
    k_scan3<<<NSCANB, 1024>>>();
    k_scatter<<<(NEDGE + 255) / 256, 256>>>(ei);
    k_xw0<<<(N_NODES + 3) / 4, dim3(64, 4)>>>(data, W1);
    k_h1<<<(N_NODES + 7) / 8, 256>>>(b1, Wp);
    k_score0<<<(N_NODES + 7) / 8, 256>>>(bp);
    k_score_rest<<<(63 * N_NODES + 255) / 256, 256>>>(data, W1, b1, Wp, bp);
    k_select<<<BATCH, 1024>>>();
    k_compact<<<dim3((N_NODES + 255) / 256, 63), 256>>>();
    k_xpw0<<<(N_NODES + 255) / 256, 256>>>(W2);
    k_h2_0<<<(N_NODES + 7) / 8, 256>>>(b2);
    k_rest<<<dim3((KTOP + 255) / 256, 63), 256>>>(data, W1, b1, W2, b2);
    k_final<<<1, 64>>>(Wf, bf, out);
}

// round 5
// speedup vs baseline: 2.0225x; 1.3251x over previous
#include <cuda_runtime.h>
#include <cuda_bf16.h>
#include <cstdint>

#define N_NODES 17186
#define KTOP    12031
#define BATCH   64
#define NEDGE   500000
#define NTOT    (BATCH * N_NODES)
#define FIN     6
#define H1DIM   64
#define H2DIM   32
#define NSCANB  ((N_NODES + 1023) / 1024)   // 17
#define XW0B    ((N_NODES + 15) / 16)       // 1075
#define S0B     ((N_NODES * 32 + 255) / 256)
#define SRB     ((63 * N_NODES + 255) / 256)
#define CXB     ((N_NODES + 255) / 256)
#define RESTB   ((KTOP + 127) / 128)        // 94
#define ASTRIDE 72                          // bf16 row stride (144B): ldmatrix conflict-free

typedef unsigned long long ull;

// ---------------- device scratch (static, no allocations) ----------------
__device__ int   g_is64;
__device__ int   g_degcnt[N_NODES];
__device__ int   g_off[N_NODES + 1];
__device__ int   g_cursor[N_NODES];
__device__ int   g_csr[NEDGE];
__device__ int   g_blksum[32];
__device__ float g_dinv0[N_NODES];
__device__ float g_xw0[N_NODES * H1DIM];
__device__ float g_h1[N_NODES * H1DIM];
__device__ float g_s0w[N_NODES];
__device__ float g_score[NTOT];
__device__ unsigned char g_kept[NTOT];
__device__ int   g_knum[BATCH];
__device__ int   g_kidx[63 * KTOP];
__device__ float g_dinv2[N_NODES];
__device__ float g_xpw[N_NODES * H2DIM];
__device__ float g_gmax[BATCH * H2DIM];

// ---------------- helpers ----------------
__device__ __forceinline__ int eidx(const void* ei, long long pos) {
    if (g_is64) return (int)((const long long*)ei)[pos];
    return ((const int*)ei)[pos];
}
__device__ __forceinline__ unsigned okey(float f) {
    unsigned u = __float_as_uint(f);
    u ^= (u & 0x80000000u) ? 0xFFFFFFFFu : 0x80000000u;
    return u;
}
__device__ __forceinline__ ull pack2(float lo, float hi) {
    ull r; asm("mov.b64 %0, {%1, %2};" : "=l"(r) : "f"(lo), "f"(hi)); return r;
}
__device__ __forceinline__ void unpack2(ull v, float& lo, float& hi) {
    asm("mov.b64 {%0, %1}, %2;" : "=f"(lo), "=f"(hi) : "l"(v));
}
__device__ __forceinline__ void ffma2(ull& d, ull a, ull b) {
    asm("fma.rn.f32x2 %0, %1, %2, %0;" : "+l"(d) : "l"(a), "l"(b));
}
__device__ __forceinline__ uint32_t smem_u32(const void* p) {
    uint32_t a;
    asm("{ .reg .u64 t; cvta.to.shared.u64 t, %1; cvt.u32.u64 %0, t; }" : "=r"(a) : "l"(p));
    return a;
}
// bf16x2 pack: low half = a, high half = b
__device__ __forceinline__ uint32_t bfpack(float a, float b) {
    uint32_t r;
    asm("cvt.rn.bf16x2.f32 %0, %1, %2;" : "=r"(r) : "f"(b), "f"(a));
    return r;
}
__device__ __forceinline__ void mma_bf16(float* c, const uint32_t* a, const uint32_t* b) {
    asm volatile(
        "mma.sync.aligned.m16n8k16.row.col.f32.bf16.bf16.f32 "
        "{%0,%1,%2,%3}, {%4,%5,%6,%7}, {%8,%9}, {%0,%1,%2,%3};"
        : "+f"(c[0]), "+f"(c[1]), "+f"(c[2]), "+f"(c[3])
        : "r"(a[0]), "r"(a[1]), "r"(a[2]), "r"(a[3]), "r"(b[0]), "r"(b[1]));
}
__device__ __forceinline__ void ldmat4(uint32_t* a, uint32_t addr) {
    asm volatile("ldmatrix.sync.aligned.m8n8.x4.shared.b16 {%0,%1,%2,%3}, [%4];"
                 : "=r"(a[0]), "=r"(a[1]), "=r"(a[2]), "=r"(a[3]) : "r"(addr));
}

// ---------------- setup kernels ----------------
__global__ void k_zero(const void* ei) {
    int i = blockIdx.x * blockDim.x + threadIdx.x;
    if (i < N_NODES) { g_degcnt[i] = 0; g_cursor[i] = 0; }
    if (i < BATCH * H2DIM) g_gmax[i] = 0.f;
    if (i < BATCH) g_knum[i] = 0;
    if (i == 0) {
        const long long* p = (const long long*)ei;
        int ok = 1;
        for (int j = 0; j < 8; j++) {
            long long v = p[j];
            if (v < 0 || v >= N_NODES) ok = 0;
        }
        g_is64 = ok;
    }
}

__global__ void k_count(const void* ei) {
    int e = blockIdx.x * blockDim.x + threadIdx.x;
    if (e < NEDGE) {
        int d = eidx(ei, (long long)NEDGE + e);
        atomicAdd(&g_degcnt[d], 1);
    }
}

// fused: blocks [0,17): scan stage 1; blocks [17,17+XW0B): xw0 = x(graph0)@W1
__global__ void k_scan1_xw0(const float* __restrict__ data, const float* __restrict__ W1) {
    __shared__ int sh[1024];
    __shared__ float W1s[FIN * H1DIM];
    int tid = threadIdx.x;
    if ((int)blockIdx.x < NSCANB) {
        int idx = blockIdx.x * 1024 + tid;
        int v = (idx < N_NODES) ? g_degcnt[idx] : 0;
        if (idx < N_NODES) g_dinv0[idx] = rsqrtf(1.0f + (float)v);
        sh[tid] = v;
        __syncthreads();
        for (int off = 1; off < 1024; off <<= 1) {
            int t = (tid >= off) ? sh[tid - off] : 0;
            __syncthreads();
            sh[tid] += t;
            __syncthreads();
        }
        if (idx < N_NODES) g_off[idx] = sh[tid] - v;
        if (tid == 1023) g_blksum[blockIdx.x] = sh[1023];
    } else {
        for (int i = tid; i < FIN * H1DIM; i += 1024) W1s[i] = W1[i];
        __syncthreads();
        int node = (blockIdx.x - NSCANB) * 16 + (tid >> 6);
        int c = tid & 63;
        if (node < N_NODES) {
            float acc = 0.f;
            #pragma unroll
            for (int k = 0; k < FIN; k++) acc += data[node * FIN + k] * W1s[k * H1DIM + c];
            g_xw0[node * 64 + ((c & 31) * 2 + (c >> 5))] = acc;
        }
    }
}

__global__ void k_scan3() {
    __shared__ int sPrefix;
    int tid = threadIdx.x;
    if (tid < 32) {
        int v = (tid < NSCANB) ? g_blksum[tid] : 0;
        int inc = v;
        #pragma unroll
        for (int off = 1; off < 32; off <<= 1) {
            int t = __shfl_up_sync(0xffffffffu, inc, off);
            if (tid >= off) inc += t;
        }
        if (tid == (int)blockIdx.x) sPrefix = inc - v;
        if (blockIdx.x == 0 && tid == NSCANB - 1) g_off[N_NODES] = inc;
    }
    __syncthreads();
    int idx = blockIdx.x * 1024 + tid;
    if (idx < N_NODES) g_off[idx] += sPrefix;
}

__global__ void k_scatter(const void* ei) {
    int e = blockIdx.x * blockDim.x + threadIdx.x;
    if (e < NEDGE) {
        int d = eidx(ei, (long long)NEDGE + e);
        int s = eidx(ei, e);
        int pos = g_off[d] + atomicAdd(&g_cursor[d], 1);
        g_csr[pos] = s;
    }
}

// h1 = relu(msg + self + b1); also s0w = h1 @ Wp  (one warp per node)
__global__ void k_h1(const float* __restrict__ b1, const float* __restrict__ Wp) {
    int w = (blockIdx.x * blockDim.x + threadIdx.x) >> 5;
    int lane = threadIdx.x & 31;
    if (w >= N_NODES) return;
    float dvi = g_dinv0[w];
    float selfw = dvi * dvi;
    float2 xw = *(const float2*)(g_xw0 + w * 64 + lane * 2);
    float a0 = xw.x * selfw;
    float a1 = xw.y * selfw;
    int s = g_off[w], e = g_off[w + 1];
    for (int j = s; j < e; j++) {
        int sr = g_csr[j];
        float nw = g_dinv0[sr] * dvi;
        float2 m = *(const float2*)(g_xw0 + sr * 64 + lane * 2);
        a0 += m.x * nw;
        a1 += m.y * nw;
    }
    a0 = fmaxf(a0 + b1[lane], 0.f);
    a1 = fmaxf(a1 + b1[32 + lane], 0.f);
    g_h1[w * 64 + lane] = a0;
    g_h1[w * 64 + 32 + lane] = a1;
    float p = a0 * Wp[lane] + a1 * Wp[32 + lane];
    #pragma unroll
    for (int off = 16; off >= 1; off >>= 1) p += __shfl_xor_sync(0xffffffffu, p, off);
    if (lane == 0) g_s0w[w] = p;
}

// fused score kernel: blocks [0,S0B) graph-0 msg-pass score; rest: graphs 1..63
__global__ void k_score(const float* __restrict__ data, const float* __restrict__ W1,
                        const float* __restrict__ b1, const float* __restrict__ Wp,
                        const float* __restrict__ bp) {
    __shared__ __align__(16) float W1s[FIN * H1DIM];
    __shared__ __align__(16) float b1s[H1DIM];
    __shared__ __align__(16) float Wps[H1DIM];
    int tid = threadIdx.x;
    if ((int)blockIdx.x < S0B) {
        int w = (blockIdx.x * 256 + tid) >> 5;
        int lane = tid & 31;
        if (w >= N_NODES) return;
        float part = 0.f;
        int s = g_off[w], e = g_off[w + 1];
        for (int j = s + lane; j < e; j += 32) {
            int sr = g_csr[j];
            part += g_s0w[sr] * g_dinv0[sr];
        }
        #pragma unroll
        for (int off = 16; off >= 1; off >>= 1) part += __shfl_xor_sync(0xffffffffu, part, off);
        if (lane == 0) {
            float dvi = g_dinv0[w];
            g_score[w] = bp[0] + g_s0w[w] * dvi * dvi + dvi * part;
        }
        return;
    }
    for (int i = tid; i < FIN * H1DIM; i += 256) W1s[i] = W1[i];
    for (int i = tid; i < H1DIM; i += 256) { b1s[i] = b1[i]; Wps[i] = Wp[i]; }
    __syncthreads();
    int gid = (blockIdx.x - S0B) * 256 + tid;
    if (gid >= 63 * N_NODES) return;
    int n = N_NODES + gid;
    const float* xr = data + (long long)n * FIN;
    ull xb[6];
    #pragma unroll
    for (int f = 0; f < FIN; f++) { float x = xr[f]; xb[f] = pack2(x, x); }
    const ull* W1p = reinterpret_cast<const ull*>(W1s);
    const ull* b1p = reinterpret_cast<const ull*>(b1s);
    const ull* Wpp = reinterpret_cast<const ull*>(Wps);
    ull acc2 = 0;
    #pragma unroll 4
    for (int c2 = 0; c2 < 32; c2++) {
        ull h2 = b1p[c2];
        #pragma unroll
        for (int f = 0; f < FIN; f++) ffma2(h2, xb[f], W1p[f * 32 + c2]);
        float h0, h1; unpack2(h2, h0, h1);
        h0 = fmaxf(h0, 0.f); h1 = fmaxf(h1, 0.f);
        ull hr = pack2(h0, h1);
        ffma2(acc2, hr, Wpp[c2]);
    }
    float a0, a1; unpack2(acc2, a0, a1);
    g_score[n] = a0 + a1 + bp[0];
}

// per-graph top-K: 3-pass radix (11/11/10) with parallel suffix-scan selection
__global__ void k_select() {
    int b = blockIdx.x;
    const float* sc = g_score + (long long)b * N_NODES;
    __shared__ int hist[2048];
    __shared__ int wsum[32];
    __shared__ unsigned sh_pref;
    __shared__ int sh_need;
    __shared__ int eqn;
    __shared__ int eql[4096];
    int tid = threadIdx.x;
    int lane = tid & 31, wid = tid >> 5;
    unsigned prefix = 0;
    int need = KTOP;
    #pragma unroll
    for (int p = 0; p < 3; p++) {
        const int shift = (p == 0) ? 21 : (p == 1) ? 10 : 0;
        const int width = (p == 2) ? 10 : 11;
        hist[tid] = 0; hist[tid + 1024] = 0;
        __syncthreads();
        for (int i = tid; i < N_NODES; i += 1024) {
            unsigned u = okey(sc[i]);
            bool ok = (p == 0) || ((u >> (shift + width)) == prefix);
            if (ok) atomicAdd(&hist[(u >> shift) & ((1u << width) - 1u)], 1);
        }
        __syncthreads();
        int v0 = 2047 - 2 * tid, v1 = 2046 - 2 * tid;
        int h0 = hist[v0], h1 = hist[v1];
        int local = h0 + h1;
        int inc = local;
        #pragma unroll
        for (int o = 1; o < 32; o <<= 1) {
            int t2 = __shfl_up_sync(0xffffffffu, inc, o);
            if (lane >= o) inc += t2;
        }
        if (lane == 31) wsum[wid] = inc;
        __syncthreads();
        if (tid < 32) {
            int w = wsum[tid];
            int wi = w;
            #pragma unroll
            for (int o = 1; o < 32; o <<= 1) {
                int t2 = __shfl_up_sync(0xffffffffu, wi, o);
                if (tid >= o) wi += t2;
            }
            wsum[tid] = wi - w;
        }
        __syncthreads();
        int prevP = wsum[wid] + (inc - local);
        if (prevP < need && need <= prevP + h0) {
            sh_pref = (prefix << width) | (unsigned)v0;
            sh_need = need - prevP;
        } else if (prevP + h0 < need && need <= prevP + h0 + h1) {
            sh_pref = (prefix << width) | (unsigned)v1;
            sh_need = need - prevP - h0;
        }
        __syncthreads();
        prefix = sh_pref;
        need = sh_need;
        __syncthreads();
    }
    unsigned tau = prefix;
    if (tid == 0) eqn = 0;
    __syncthreads();
    for (int i = tid; i < N_NODES; i += 1024) {
        unsigned u = okey(sc[i]);
        g_kept[(long long)b * N_NODES + i] = (u > tau) ? 1 : 0;
        if (u == tau) {
            int p = atomicAdd(&eqn, 1);
            if (p < 4096) eql[p] = i;
        }
    }
    __syncthreads();
    int ne = min(eqn, 4096);
    for (int t = tid; t < ne; t += 1024) {
        int idx = eql[t];
        int rank = 0;
        for (int j = 0; j < ne; j++) rank += (eql[j] < idx);
        if (rank < need) g_kept[(long long)b * N_NODES + idx] = 1;
    }
}

// fused: y==0 -> graph-0 dinv2 + xpw;  y>=1 -> compact kept ids for graph y
__global__ void k_cx(const float* __restrict__ W2) {
    int tid = threadIdx.x;
    if (blockIdx.y > 0) {
        int nig = blockIdx.x * blockDim.x + tid;
        int bg = blockIdx.y;
        bool kp = (nig < N_NODES) && g_kept[bg * N_NODES + nig];
        unsigned mask = __ballot_sync(0xffffffffu, kp);
        if (!mask) return;
        int lane = tid & 31;
        int leader = __ffs(mask) - 1;
        int base = 0;
        if (lane == leader) base = atomicAdd(&g_knum[bg], __popc(mask));
        base = __shfl_sync(0xffffffffu, base, leader);
        if (kp) {
            int pos = base + __popc(mask & ((1u << lane) - 1u));
            g_kidx[(bg - 1) * KTOP + pos] = nig;
        }
        return;
    }
    __shared__ __align__(16) float W2s[H1DIM * H2DIM];
    for (int i = tid; i < H1DIM * H2DIM; i += 256) W2s[i] = W2[i];
    __syncthreads();
    int n = blockIdx.x * blockDim.x + tid;
    if (n >= N_NODES) return;
    if (!g_kept[n]) {
        g_dinv2[n] = 0.f;
        #pragma unroll
        for (int c = 0; c < H2DIM; c++) g_xpw[n * H2DIM + c] = 0.f;
        return;
    }
    {
        int cnt = 0;
        int s = g_off[n], e = g_off[n + 1];
        for (int j = s; j < e; j++) cnt += g_kept[g_csr[j]];
        g_dinv2[n] = rsqrtf(1.0f + (float)cnt);
    }
    float t = tanhf(g_score[n]);
    const ull* W2p = reinterpret_cast<const ull*>(W2s);
    ull acc2[16];
    #pragma unroll
    for (int c2 = 0; c2 < 16; c2++) acc2[c2] = 0;
    const float4* hr = (const float4*)(g_h1 + n * H1DIM);
    #pragma unroll 4
    for (int k4 = 0; k4 < 16; k4++) {
        float4 h4 = hr[k4];
        ull hb0 = pack2(h4.x, h4.x), hb1 = pack2(h4.y, h4.y);
        ull hb2 = pack2(h4.z, h4.z), hb3 = pack2(h4.w, h4.w);
        const ull* w = W2p + (k4 * 4) * 16;
        #pragma unroll
        for (int c2 = 0; c2 < 16; c2++) {
            ffma2(acc2[c2], hb0, w[c2]);
            ffma2(acc2[c2], hb1, w[16 + c2]);
            ffma2(acc2[c2], hb2, w[32 + c2]);
            ffma2(acc2[c2], hb3, w[48 + c2]);
        }
    }
    #pragma unroll
    for (int c2 = 0; c2 < 16; c2++) {
        float lo, hi; unpack2(acc2[c2], lo, hi);
        g_xpw[n * H2DIM + 2 * c2] = t * lo;
        g_xpw[n * H2DIM + 2 * c2 + 1] = t * hi;
    }
}

// graph 0 conv2 + relu + max-pool into g_gmax[0..31]
__global__ void k_h2_0(const float* __restrict__ b2) {
    __shared__ int smax[H2DIM];
    int tid = threadIdx.x;
    if (tid < H2DIM) smax[tid] = 0;
    __syncthreads();
    int w = blockIdx.x * 8 + (tid >> 5);
    int lane = tid & 31;
    float v = 0.f;
    if (w < N_NODES && g_kept[w]) {
        float dvi = g_dinv2[w];
        float acc = g_xpw[w * H2DIM + lane] * dvi * dvi;
        int s = g_off[w], e = g_off[w + 1];
        for (int j = s; j < e; j++) {
            int sr = g_csr[j];
            acc += g_xpw[sr * H2DIM + lane] * (g_dinv2[sr] * dvi);
        }
        v = fmaxf(acc + b2[lane], 0.f);
    }
    atomicMax(&smax[lane], __float_as_int(v));
    __syncthreads();
    if (tid < H2DIM)
        atomicMax(reinterpret_cast<int*>(&g_gmax[tid]), smax[tid]);
}

// graphs 1..63: HMMA (mma.sync bf16, split precision) 128x32x64 per CTA
__global__ void k_rest_mma(const float* __restrict__ data, const float* __restrict__ W1,
                           const float* __restrict__ b1, const float* __restrict__ W2,
                           const float* __restrict__ b2) {
    __shared__ __align__(16) __nv_bfloat16 Ah[128 * ASTRIDE];
    __shared__ __align__(16) __nv_bfloat16 Al[128 * ASTRIDE];
    __shared__ __align__(16) float W2s[H1DIM * H2DIM];   // [k][c]
    __shared__ __align__(16) float W1s[FIN * H1DIM];
    __shared__ __align__(16) float b1s[H1DIM];
    __shared__ float b2s[H2DIM];
    __shared__ int smax[H2DIM];

    int tid = threadIdx.x, wid = tid >> 5, lane = tid & 31;
    for (int i = tid; i < FIN * H1DIM; i += 128) W1s[i] = W1[i];
    if (tid < H1DIM) b1s[tid] = b1[tid];
    if (tid < H2DIM) { b2s[tid] = b2[tid]; smax[tid] = 0; }
    for (int i = tid; i < H1DIM * H2DIM; i += 128) W2s[i] = W2[i];

    int i0 = blockIdx.x * 128;
    int bg = blockIdx.y + 1;
    bool valid = (i0 + tid) < KTOP;
    int n = bg * N_NODES + (valid ? g_kidx[(bg - 1) * KTOP + i0 + tid] : 0);
    float t = valid ? tanhf(g_score[n]) : 0.f;
    const float* xr = data + (long long)n * FIN;
    ull xb[6];
    #pragma unroll
    for (int f = 0; f < FIN; f++) { float x = xr[f]; xb[f] = pack2(x, x); }
    __syncthreads();   // W1s/b1s ready

    // produce A row: t * relu(x@W1 + b1), bf16 hi + residual lo
    const ull* W1p = reinterpret_cast<const ull*>(W1s);
    const ull* b1p = reinterpret_cast<const ull*>(b1s);
    char* ahrow = reinterpret_cast<char*>(Ah) + tid * (ASTRIDE * 2);
    char* alrow = reinterpret_cast<char*>(Al) + tid * (ASTRIDE * 2);
    #pragma unroll 4
    for (int k2 = 0; k2 < 32; k2++) {
        ull h2 = b1p[k2];
        #pragma unroll
        for (int f = 0; f < FIN; f++) ffma2(h2, xb[f], W1p[f * 32 + k2]);
        float h0, h1; unpack2(h2, h0, h1);
        h0 = fmaxf(h0, 0.f) * t;
        h1 = fmaxf(h1, 0.f) * t;
        uint32_t hi = bfpack(h0, h1);
        float r0 = h0 - __uint_as_float(hi << 16);
        float r1 = h1 - __uint_as_float(hi & 0xFFFF0000u);
        uint32_t lo = bfpack(r0, r1);
        *reinterpret_cast<uint32_t*>(ahrow + k2 * 4) = hi;
        *reinterpret_cast<uint32_t*>(alrow + k2 * 4) = lo;
    }
    __syncthreads();   // A tiles ready

    // mma mainloop: each warp owns rows [wid*32, wid*32+32)
    float acc[2][4][4];
    #pragma unroll
    for (int mt = 0; mt < 2; mt++)
        #pragma unroll
        for (int nt = 0; nt < 4; nt++)
            #pragma unroll
            for (int r = 0; r < 4; r++) acc[mt][nt][r] = 0.f;

    int lrow = (lane & 7) + ((lane >> 3) & 1) * 8;  // row-within-16 for ldmatrix
    int khalf = lane >> 4;
    int q = lane & 3, rg = lane >> 2;
    uint32_t ah_base = smem_u32(Ah), al_base = smem_u32(Al);

    #pragma unroll
    for (int kt = 0; kt < 4; kt++) {
        uint32_t af[2][4], alf[2][4];
        #pragma unroll
        for (int mt = 0; mt < 2; mt++) {
            uint32_t off = (wid * 32 + mt * 16 + lrow) * (ASTRIDE * 2) + kt * 32 + khalf * 16;
            ldmat4(af[mt], ah_base + off);
            ldmat4(alf[mt], al_base + off);
        }
        // B fragments (hi + residual), built from f32 smem
        uint32_t bh[4][2], bl[4][2];
        #pragma unroll
        for (int nt = 0; nt < 4; nt++) {
            int col = nt * 8 + rg;
            #pragma unroll
            for (int h = 0; h < 2; h++) {
                int k0 = kt * 16 + 2 * q + h * 8;
                float w0 = W2s[k0 * H2DIM + col];
                float w1 = W2s[(k0 + 1) * H2DIM + col];
                uint32_t hi = bfpack(w0, w1);
                float r0 = w0 - __uint_as_float(hi << 16);
                float r1 = w1 - __uint_as_float(hi & 0xFFFF0000u);
                bh[nt][h] = hi;
                bl[nt][h] = bfpack(r0, r1);
            }
        }
        #pragma unroll
        for (int mt = 0; mt < 2; mt++)
            #pragma unroll
            for (int nt = 0; nt < 4; nt++) {
                mma_bf16(acc[mt][nt], af[mt], bh[nt]);
                mma_bf16(acc[mt][nt], af[mt], bl[nt]);
                mma_bf16(acc[mt][nt], alf[mt], bh[nt]);
            }
    }

    // epilogue: relu(D + b2) masked by row validity, per-channel max
    #pragma unroll
    for (int nt = 0; nt < 4; nt++) {
        int col0 = nt * 8 + 2 * q;
        float me = 0.f, mo = 0.f;
        #pragma unroll
        for (int mt = 0; mt < 2; mt++) {
            int r0 = i0 + wid * 32 + mt * 16 + rg;
            bool v0 = r0 < KTOP, v1 = (r0 + 8) < KTOP;
            float e0 = v0 ? fmaxf(acc[mt][nt][0] + b2s[col0], 0.f) : 0.f;
            float e1 = v0 ? fmaxf(acc[mt][nt][1] + b2s[col0 + 1], 0.f) : 0.f;
            float e2 = v1 ? fmaxf(acc[mt][nt][2] + b2s[col0], 0.f) : 0.f;
            float e3 = v1 ? fmaxf(acc[mt][nt][3] + b2s[col0 + 1], 0.f) : 0.f;
            me = fmaxf(me, fmaxf(e0, e2));
            mo = fmaxf(mo, fmaxf(e1, e3));
        }
        #pragma unroll
        for (int off = 4; off < 32; off <<= 1) {
            me = fmaxf(me, __shfl_xor_sync(0xffffffffu, me, off));
            mo = fmaxf(mo, __shfl_xor_sync(0xffffffffu, mo, off));
        }
        if (rg == 0) {
            atomicMax(&smax[col0], __float_as_int(me));
            atomicMax(&smax[col0 + 1], __float_as_int(mo));
        }
    }
    __syncthreads();
    if (tid < H2DIM)
        atomicMax(reinterpret_cast<int*>(&g_gmax[bg * H2DIM + tid]), smax[tid]);
}

__global__ void k_final(const float* __restrict__ Wf, const float* __restrict__ bf,
                        float* __restrict__ out) {
    int b = threadIdx.x;
    if (b >= BATCH) return;
    float acc = bf[0];
    #pragma unroll
    for (int c = 0; c < H2DIM; c++) acc += g_gmax[b * H2DIM + c] * Wf[c];
    out[b] = 1.f / (1.f + expf(-acc));
}

// ---------------- launch ----------------
extern "C" void kernel_launch(void* const* d_in, const int* in_sizes, int n_in,
                              void* d_out, int out_size) {
    const float* data = (const float*)d_in[0];
    const void*  ei   = d_in[1];
    const float* W1   = (const float*)d_in[2];
    const float* b1   = (const float*)d_in[3];
    const float* Wp   = (const float*)d_in[4];
    const float* bp   = (const float*)d_in[5];
    const float* W2   = (const float*)d_in[6];
    const float* b2   = (const float*)d_in[7];
    const float* Wf   = (const float*)d_in[8];
    const float* bf   = (const float*)d_in[9];
    float* out = (float*)d_out;

    k_zero<<<(N_NODES + 255) / 256, 256>>>(ei);
    k_count<<<(NEDGE + 255) / 256, 256>>>(ei);
    k_scan1_xw0<<<NSCANB + XW0B, 1024>>>(data, W1);
    k_scan3<<<NSCANB, 1024>>>();
    k_scatter<<<(NEDGE + 255) / 256, 256>>>(ei);
    k_h1<<<(N_NODES + 7) / 8, 256>>>(b1, Wp);
    k_score<<<S0B + SRB, 256>>>(data, W1, b1, Wp, bp);
    k_select<<<BATCH, 1024>>>();
    k_cx<<<dim3(CXB, BATCH), 256>>>(W2);
    k_h2_0<<<(N_NODES + 7) / 8, 256>>>(b2);
    k_rest_mma<<<dim3(RESTB, 63), 128>>>(data, W1, b1, W2, b2);
    k_final<<<1, 64>>>(Wf, bf, out);
}